// round 10
// baseline (speedup 1.0000x reference)
#include <cuda_runtime.h>
#include <stdint.h>

// Problem constants (fixed by dataset)
#define S_TOK   16384
#define C_DIM   1280
#define C3      3840
#define D_HEAD  80
#define BLK     16
#define NBLK    (S_TOK / BLK)   // 1024
#define KDIM    1280
#define KB8     (KDIM / 8)      // 160

// Scratch (__device__ globals; no allocation allowed)
__device__ float    g_qkv[(size_t)S_TOK * C3];          // permuted-order QKV (fp32, row-major)
__device__ uint32_t g_xt [(size_t)S_TOK * KDIM];        // x gathered+tf32, A-frag layout
__device__ uint32_t g_y  [(size_t)S_TOK * KDIM];        // attn out tf32, A-frag layout (orig order)
__device__ uint32_t g_wqkvF [(size_t)(C3   / 64) * KB8 * 832]; // W_qkv  B-frag layout
__device__ uint32_t g_wprojF[(size_t)(C_DIM / 64) * KB8 * 832]; // W_proj B-frag layout

// ---------------------------------------------------------------------------
__device__ __forceinline__ uint32_t f2tf(float f) {
    uint32_t r; asm("cvt.rna.tf32.f32 %0, %1;" : "=r"(r) : "f"(f)); return r;
}
// A-fragment layout (any M, K=1280):
__device__ __forceinline__ size_t addrA(int m, int k) {
    return ((size_t)((m >> 4) * KB8 + (k >> 3)) << 7)
         + ((m & 7) << 4) + ((k & 3) << 2) + (((k >> 2) & 1) << 1) + ((m >> 3) & 1);
}
// B-fragment layout (weights K x N, K=1280):
__device__ __forceinline__ size_t addrB(int k, int n) {
    return (size_t)((n >> 6) * KB8 + (k >> 3)) * 832
         + (size_t)(k & 7) * 104 + (n & 7) * 12 + ((n >> 3) & 7);
}
__device__ __forceinline__ void cpa16(uint32_t dst, const void* src) {
    asm volatile("cp.async.cg.shared.global [%0], [%1], 16;" :: "r"(dst), "l"(src) : "memory");
}
__device__ __forceinline__ void cpa_commit() {
    asm volatile("cp.async.commit_group;" ::: "memory");
}
__device__ __forceinline__ void cpa_wait2() {
    asm volatile("cp.async.wait_group 2;" ::: "memory");
}
__device__ __forceinline__ uint32_t smem_u32(const void* p) {
    uint32_t a;
    asm("{ .reg .u64 t; cvta.to.shared.u64 t, %1; cvt.u32.u64 %0, t; }" : "=r"(a) : "l"(p));
    return a;
}
__device__ __forceinline__ void mma_tf32(float* d, const uint32_t* a, const uint32_t* b) {
    asm volatile(
        "mma.sync.aligned.m16n8k8.row.col.f32.tf32.tf32.f32 "
        "{%0,%1,%2,%3}, {%4,%5,%6,%7}, {%8,%9}, {%0,%1,%2,%3};"
        : "+f"(d[0]), "+f"(d[1]), "+f"(d[2]), "+f"(d[3])
        : "r"(a[0]), "r"(a[1]), "r"(a[2]), "r"(a[3]),
          "r"(b[0]), "r"(b[1]));
}

// ---------------------------------------------------------------------------
// TF32 mma.sync GEMM, fragment-native smem (all frag loads = LDS.128).
// CTA 128x128, BK=16, 128 thr (4 warps 2x2), warp tile 64x64.
// 4-stage cp.async; k-loop unrolled by 4 so stage offsets are immediates.
// Per iter: batch all 16 LDS.128, then 64 back-to-back MMAs.
// ---------------------------------------------------------------------------
#define BM 128
#define BN 128
#define BK 16
#define A_STAGE_W 2048
#define B_STAGE_W 3328
#define ST_W (A_STAGE_W + B_STAGE_W)     // 5376 words
#define NSTAGE 4
#define SMEM_BYTES (NSTAGE * ST_W * 4)   // 86016

__global__ __launch_bounds__(128, 2)
void mma_gemm_frag(const uint32_t* __restrict__ A, const uint32_t* __restrict__ B,
                   float* __restrict__ C, int N)
{
    extern __shared__ char smem[];
    const uint32_t sb = smem_u32(smem);
    uint32_t* smw = (uint32_t*)smem;

    const int tid  = threadIdx.x;
    const int bx   = blockIdx.x, by = blockIdx.y;
    const int warp = tid >> 5, lane = tid & 31;
    const int wm   = warp >> 1, wn = warp & 1;   // 2x2 warp grid
    const int g    = lane >> 2, t = lane & 3;

    // ---- producer mapping: A 4 chunks + B <=7 chunks (16B) per thread ----
    const uint32_t* Asrc[4];
    uint32_t a_dst[4];
    #pragma unroll
    for (int j = 0; j < 4; j++) {
        int c  = tid + 128 * j;
        int rg = c >> 6, cc = c & 63;
        Asrc[j] = A + ((size_t)(by * 8 + rg) * KB8) * 128 + cc * 4;
        a_dst[j] = (uint32_t)c * 16;
    }
    const uint32_t* Bsrc[7];
    uint32_t b_dst[7];
    int nb = 0;
    #pragma unroll
    for (int j = 0; j < 7; j++) {
        int c = tid + 128 * j;
        if (c < 832) {
            int ngl = (c >= 416) ? 1 : 0;
            int cc  = c - ngl * 416;
            Bsrc[nb] = B + (size_t)(bx * 2 + ngl) * KB8 * 832 + cc * 4;
            b_dst[nb] = (uint32_t)(A_STAGE_W * 4) + (uint32_t)c * 16;
            nb++;
        }
    }

    // ---- hoisted consumer fragment bases (word offsets within a stage) ----
    //   A frag for (mt, ks8): a_base + mt*256 + ks8*128   (one uint4)
    //   B frag for (ks8, krow, half): b_base + ks8*832 + krow*416(=4*104) + half*4
    const uint32_t a_base = (uint32_t)(wm * 1024 + g * 16 + t * 4);
    const uint32_t b_base = (uint32_t)(A_STAGE_W + wn * 1664 + t * 104 + g * 12);

    float acc[4][8][4];
    #pragma unroll
    for (int mt = 0; mt < 4; mt++)
        #pragma unroll
        for (int nt = 0; nt < 8; nt++)
            #pragma unroll
            for (int i = 0; i < 4; i++) acc[mt][nt][i] = 0.f;

    const int NIT = KDIM / BK;   // 80 (divisible by NSTAGE)

    // ---- prologue: issue stages 0..2 ----
    #pragma unroll
    for (int s = 0; s < NSTAGE - 1; s++) {
        const uint32_t so = sb + s * (ST_W * 4);
        const int kt8 = s * 2;
        #pragma unroll
        for (int j = 0; j < 4; j++)
            cpa16(so + a_dst[j], Asrc[j] + (size_t)kt8 * 128);
        for (int j = 0; j < nb; j++)
            cpa16(so + b_dst[j], Bsrc[j] + (size_t)kt8 * 832);
        cpa_commit();
    }

    #pragma unroll 1
    for (int blk = 0; blk < NIT; blk += NSTAGE) {
        #pragma unroll
        for (int s = 0; s < NSTAGE; s++) {     // stage == s (compile-time)
            const int i = blk + s;
            cpa_wait2();
            __syncthreads();

            if (i + NSTAGE - 1 < NIT) {
                const int s3 = (s + NSTAGE - 1) & (NSTAGE - 1);
                const uint32_t so = sb + s3 * (ST_W * 4);
                const int kt8 = (i + NSTAGE - 1) * 2;
                #pragma unroll
                for (int j = 0; j < 4; j++)
                    cpa16(so + a_dst[j], Asrc[j] + (size_t)kt8 * 128);
                for (int j = 0; j < nb; j++)
                    cpa16(so + b_dst[j], Bsrc[j] + (size_t)kt8 * 832);
            }
            cpa_commit();

            // ---- batch ALL fragment loads for this stage (16 x LDS.128) ----
            const uint32_t* As = smw + s * ST_W + a_base;
            const uint32_t* Bb = smw + s * ST_W + b_base;

            uint32_t af[2][4][4];
            uint32_t bfr[2][2][8];   // [ks8][krow(t / t+4)][nt]
            #pragma unroll
            for (int ks8 = 0; ks8 < 2; ks8++) {
                #pragma unroll
                for (int mt = 0; mt < 4; mt++)
                    *(uint4*)af[ks8][mt] =
                        *(const uint4*)(As + mt * 256 + ks8 * 128);
                *(uint4*)&bfr[ks8][0][0] = *(const uint4*)(Bb + ks8 * 832);
                *(uint4*)&bfr[ks8][0][4] = *(const uint4*)(Bb + ks8 * 832 + 4);
                *(uint4*)&bfr[ks8][1][0] = *(const uint4*)(Bb + ks8 * 832 + 416);
                *(uint4*)&bfr[ks8][1][4] = *(const uint4*)(Bb + ks8 * 832 + 420);
            }

            // ---- 64 MMAs back-to-back ----
            #pragma unroll
            for (int ks8 = 0; ks8 < 2; ks8++)
                #pragma unroll
                for (int mt = 0; mt < 4; mt++)
                    #pragma unroll
                    for (int nt = 0; nt < 8; nt++) {
                        uint32_t bb[2] = { bfr[ks8][0][nt], bfr[ks8][1][nt] };
                        mma_tf32(acc[mt][nt], af[ks8][mt], bb);
                    }
        }
    }

    // ---- epilogue (row-major C) ----
    #pragma unroll
    for (int mt = 0; mt < 4; mt++) {
        const int row0 = by * BM + wm * 64 + mt * 16 + g;
        #pragma unroll
        for (int nt = 0; nt < 8; nt++) {
            const int col = bx * BN + wn * 64 + nt * 8 + t * 2;
            *(float2*)(C + (size_t)row0 * N + col) =
                make_float2(acc[mt][nt][0], acc[mt][nt][1]);
            *(float2*)(C + (size_t)(row0 + 8) * N + col) =
                make_float2(acc[mt][nt][2], acc[mt][nt][3]);
        }
    }
}

// ---------------------------------------------------------------------------
// x -> gathered rows, tf32, A-fragment layout
// ---------------------------------------------------------------------------
__global__ __launch_bounds__(256)
void cvt_x_gather_kernel(const float* __restrict__ x, uint32_t* __restrict__ xt,
                         const int* __restrict__ win)
{
    int i = blockIdx.x * 256 + threadIdx.x;       // S_TOK*320 threads
    int s  = i / (KDIM / 4);
    int c4 = (i % (KDIM / 4)) * 4;
    float4 v = *(const float4*)(x + (size_t)win[s] * KDIM + c4);
    size_t a0 = addrA(s, c4);
    xt[a0 +  0] = f2tf(v.x);
    xt[a0 +  4] = f2tf(v.y);
    xt[a0 +  8] = f2tf(v.z);
    xt[a0 + 12] = f2tf(v.w);
}

// ---------------------------------------------------------------------------
// W[K,N] fp32 row-major -> tf32 B-fragment layout
// ---------------------------------------------------------------------------
__global__ __launch_bounds__(256)
void cvt_w_frag_kernel(const float* __restrict__ W, uint32_t* __restrict__ WF, int N)
{
    int i = blockIdx.x * 256 + threadIdx.x;       // KDIM*(N/4) threads
    int k  = i / (N / 4);
    int n4 = (i % (N / 4)) * 4;
    float4 v = *(const float4*)(W + (size_t)k * N + n4);
    WF[addrB(k, n4 + 0)] = f2tf(v.x);
    WF[addrB(k, n4 + 1)] = f2tf(v.y);
    WF[addrB(k, n4 + 2)] = f2tf(v.z);
    WF[addrB(k, n4 + 3)] = f2tf(v.w);
}

// ---------------------------------------------------------------------------
// Windowed attention, RoPE fused; scatters y (tf32) into A-frag layout,
// rows in ORIGINAL token order (feeds GEMM2 directly).
// ---------------------------------------------------------------------------
__global__ __launch_bounds__(256)
void attn_kernel(const float* __restrict__ qkv, uint32_t* __restrict__ y,
                 const int* __restrict__ win,
                 const float* __restrict__ cosp, const float* __restrict__ sinp)
{
    const int b = blockIdx.x >> 4;
    const int h = blockIdx.x & 15;

    __shared__ float qs[BLK][D_HEAD + 1];
    __shared__ float ks[BLK][D_HEAD + 1];
    __shared__ float vs[BLK][D_HEAD + 1];
    __shared__ float att[BLK][BLK + 1];
    __shared__ int   toks[BLK];

    const int tid = threadIdx.x;
    if (tid < BLK) toks[tid] = win[b * BLK + tid];
    __syncthreads();

    for (int tdx = tid; tdx < BLK * D_HEAD; tdx += 256) {
        int i = tdx / D_HEAD, d = tdx % D_HEAD;
        size_t base = (size_t)(b * BLK + i) * C3 + (size_t)h * D_HEAD + d;
        float q = qkv[base];
        float k = qkv[base + C_DIM];
        float v = qkv[base + 2 * C_DIM];
        int tok = toks[i];
        float cv = cosp[(size_t)tok * D_HEAD + d];
        float sv = sinp[(size_t)tok * D_HEAD + d];
        qs[i][d] = q * cv + k * sv;
        ks[i][d] = k * cv - q * sv;
        vs[i][d] = v;
    }
    __syncthreads();

    {
        int i = tid >> 4, j = tid & 15;
        float sc = 0.f;
        #pragma unroll
        for (int d = 0; d < D_HEAD; d++) sc += qs[i][d] * ks[j][d];
        att[i][j] = sc * 0.11180339887498949f;   // 1/sqrt(80)
    }
    __syncthreads();

    if (tid < BLK) {
        float m = -1e30f;
        #pragma unroll
        for (int j = 0; j < BLK; j++) m = fmaxf(m, att[tid][j]);
        float sum = 0.f;
        #pragma unroll
        for (int j = 0; j < BLK; j++) {
            float e = __expf(att[tid][j] - m);
            att[tid][j] = e;
            sum += e;
        }
        float inv = 1.f / sum;
        #pragma unroll
        for (int j = 0; j < BLK; j++) att[tid][j] *= inv;
    }
    __syncthreads();

    for (int tdx = tid; tdx < BLK * D_HEAD; tdx += 256) {
        int i = tdx / D_HEAD, d = tdx % D_HEAD;
        float a = 0.f;
        #pragma unroll
        for (int j = 0; j < BLK; j++) a += att[i][j] * vs[j][d];
        y[addrA(toks[i], h * D_HEAD + d)] = f2tf(a);
    }
}

// ---------------------------------------------------------------------------
extern "C" void kernel_launch(void* const* d_in, const int* in_sizes, int n_in,
                              void* d_out, int out_size)
{
    const float* x     = (const float*)d_in[0];
    const float* cosp  = (const float*)d_in[1];
    const float* sinp  = (const float*)d_in[2];
    const float* Wqkv  = (const float*)d_in[3];
    const float* Wproj = (const float*)d_in[4];
    const int*   win   = (const int*)  d_in[5];
    float* out = (float*)d_out;

    float *qkv_ptr;
    uint32_t *xt_ptr, *y_ptr, *wqkv_ptr, *wproj_ptr;
    cudaGetSymbolAddress((void**)&qkv_ptr,   g_qkv);
    cudaGetSymbolAddress((void**)&xt_ptr,    g_xt);
    cudaGetSymbolAddress((void**)&y_ptr,     g_y);
    cudaGetSymbolAddress((void**)&wqkv_ptr,  g_wqkvF);
    cudaGetSymbolAddress((void**)&wproj_ptr, g_wprojF);

    cudaFuncSetAttribute(mma_gemm_frag,
        cudaFuncAttributeMaxDynamicSharedMemorySize, SMEM_BYTES);

    // 0) pre-permute inputs: x (gather + tf32 + A-frag), weights (tf32 + B-frag)
    cvt_x_gather_kernel<<<(S_TOK * (KDIM / 4)) / 256, 256>>>(x, xt_ptr, win);
    cvt_w_frag_kernel<<<(KDIM * (C3 / 4)) / 256, 256>>>(Wqkv, wqkv_ptr, C3);
    cvt_w_frag_kernel<<<(KDIM * (C_DIM / 4)) / 256, 256>>>(Wproj, wproj_ptr, C_DIM);

    // 1) QKV GEMM: g_qkv = g_xt @ W_qkv   (gather already applied)
    {
        dim3 grid(C3 / BN, S_TOK / BM);   // 30 x 128
        mma_gemm_frag<<<grid, 128, SMEM_BYTES>>>(xt_ptr, wqkv_ptr, qkv_ptr, C3);
    }

    // 2) Windowed attention (RoPE fused) -> g_y (A-frag layout, original order)
    attn_kernel<<<NBLK * 16, 256>>>(qkv_ptr, y_ptr, win, cosp, sinp);

    // 3) Output projection: out = g_y @ W_proj
    {
        dim3 grid(C_DIM / BN, S_TOK / BM);  // 10 x 128
        mma_gemm_frag<<<grid, 128, SMEM_BYTES>>>(y_ptr, wproj_ptr, out, C_DIM);
    }
}